// round 4
// baseline (speedup 1.0000x reference)
#include <cuda_runtime.h>

// QModel_43885975830736 — constant-output identity (proven R1, rel_err 3e-7):
// wire 8 is never touched by any gate, so its |1> amplitude block stays
// exactly zero; all gates are unitary and the embedding normalizes, so
// probs(wire 8) == [1, 0] for every batch row, independent of x and weights.
//
// We are at the graph-replay launch-overhead floor (kernel dur pinned at
// ~3.4-3.6us for 3 different geometries; DRAM 0.0%). This round: minimal
// block-dispatch count — 8 blocks x 128 threads, 4 unrolled 256-bit stores
// per thread (1024 threads * 32 floats = 32768 floats exactly).

__global__ void __launch_bounds__(128, 1)
qmodel_fill8x4(float* __restrict__ out) {
    unsigned tid = blockIdx.x * 128u + threadIdx.x;   // 0..1023
    float* p = out + (size_t)tid * 32u;
#pragma unroll
    for (int j = 0; j < 4; j++) {
        asm volatile(
            "st.global.v8.f32 [%0], {%1, %2, %1, %2, %1, %2, %1, %2};"
            :: "l"(p + j * 8), "f"(1.0f), "f"(0.0f)
            : "memory");
    }
}

// Guarded fallback for any unexpected out_size.
__global__ void __launch_bounds__(256, 1)
qmodel_fill_guarded(float* __restrict__ out, int n) {
    int i = blockIdx.x * 256 + threadIdx.x;
    if (i < n) out[i] = (i & 1) ? 0.0f : 1.0f;
}

extern "C" void kernel_launch(void* const* d_in, const int* in_sizes, int n_in,
                              void* d_out, int out_size) {
    (void)d_in; (void)in_sizes; (void)n_in;
    if (out_size == 32768) {
        qmodel_fill8x4<<<8, 128>>>((float*)d_out);
        return;
    }
    int blocks = (out_size + 255) / 256;
    if (blocks < 1) blocks = 1;
    qmodel_fill_guarded<<<blocks, 256>>>((float*)d_out, out_size);
}

// round 5
// speedup vs baseline: 1.3185x; 1.3185x over previous
#include <cuda_runtime.h>

// QModel_43885975830736 — constant-output identity (proven R1, rel_err 3e-7):
// wire 8 is never acted on by any gate; its |1> amplitude block is exactly
// zero through the whole circuit; all gates are unitary and the embedding is
// normalized, so probs(wire 8) == [1, 0] for every batch row, independent of
// x and weights.
//
// Converged configuration (R3, measured best at 4.83us): we are at the
// graph-replay launch-overhead floor (kernel dur ~3.45us regardless of work;
// DRAM 0.0%). One 256-bit store per thread, single wave of 16 blocks x 256
// threads (4096 threads * 8 floats = 32768 floats exactly), 16 regs, one
// pointer param. R2 (more blocks) and R4 (fatter threads, 38 regs) both
// measured slower — this shape is the empirical optimum.

__global__ void __launch_bounds__(256, 1)
qmodel_fill8(float* __restrict__ out) {
    unsigned idx = blockIdx.x * 256u + threadIdx.x;
    float* p = out + (size_t)idx * 8u;
    asm volatile(
        "st.global.v8.f32 [%0], {%1, %2, %1, %2, %1, %2, %1, %2};"
        :: "l"(p), "f"(1.0f), "f"(0.0f)
        : "memory");
}

// Guarded fallback for any unexpected out_size.
__global__ void __launch_bounds__(256, 1)
qmodel_fill_guarded(float* __restrict__ out, int n) {
    int i = blockIdx.x * 256 + threadIdx.x;
    if (i < n) out[i] = (i & 1) ? 0.0f : 1.0f;
}

extern "C" void kernel_launch(void* const* d_in, const int* in_sizes, int n_in,
                              void* d_out, int out_size) {
    (void)d_in; (void)in_sizes; (void)n_in;
    if ((out_size & 2047) == 0 && out_size > 0) {
        int threads_total = out_size >> 3;   // one v8 store each
        int blocks = threads_total >> 8;     // /256, exact by the mask check
        qmodel_fill8<<<blocks, 256>>>((float*)d_out);
        return;
    }
    int blocks = (out_size + 255) / 256;
    if (blocks < 1) blocks = 1;
    qmodel_fill_guarded<<<blocks, 256>>>((float*)d_out, out_size);
}

// round 6
// speedup vs baseline: 1.4476x; 1.0979x over previous
#include <cuda_runtime.h>

// QModel_43885975830736 — FINAL (converged R3/R5 configuration).
//
// Math identity (R1, rel_err 3.07e-7 stable across 5 runs): wire 8 is never
// acted on by any gate, so its |1> amplitude block remains exactly zero;
// all gates are unitary and the embedding is normalized, hence
// probs(wire 8) == [1, 0] for every batch row, independent of x and weights.
// The entire workload reduces to writing the 1,0,1,0,... pattern (128 KB).
//
// Perf: pinned at the graph-replay launch-overhead floor. Kernel dur
// 3.33-3.46us across runs with DRAM 0.0% — the store traffic is invisible.
// Probed axes (all worse or noise): more blocks (R2 +0.2us), fatter threads
// (R4 +0.6us, regs 16->38), v4 vs v8 (noise). Optimum: single wave,
// 16 blocks x 256 threads, one 256-bit store per thread, 16 regs, one param.

__global__ void __launch_bounds__(256, 1)
qmodel_fill8(float* __restrict__ out) {
    unsigned idx = blockIdx.x * 256u + threadIdx.x;
    float* p = out + (size_t)idx * 8u;
    asm volatile(
        "st.global.v8.f32 [%0], {%1, %2, %1, %2, %1, %2, %1, %2};"
        :: "l"(p), "f"(1.0f), "f"(0.0f)
        : "memory");
}

// Guarded fallback for any unexpected out_size.
__global__ void __launch_bounds__(256, 1)
qmodel_fill_guarded(float* __restrict__ out, int n) {
    int i = blockIdx.x * 256 + threadIdx.x;
    if (i < n) out[i] = (i & 1) ? 0.0f : 1.0f;
}

extern "C" void kernel_launch(void* const* d_in, const int* in_sizes, int n_in,
                              void* d_out, int out_size) {
    (void)d_in; (void)in_sizes; (void)n_in;
    if ((out_size & 2047) == 0 && out_size > 0) {
        int threads_total = out_size >> 3;   // one v8 store each
        int blocks = threads_total >> 8;     // /256, exact by the mask check
        qmodel_fill8<<<blocks, 256>>>((float*)d_out);
        return;
    }
    int blocks = (out_size + 255) / 256;
    if (blocks < 1) blocks = 1;
    qmodel_fill_guarded<<<blocks, 256>>>((float*)d_out, out_size);
}